// round 5
// baseline (speedup 1.0000x reference)
#include <cuda_runtime.h>
#include <cuda_bf16.h>
#include <math.h>
#include <stdint.h>

// ---------------- model constants ----------------
#define BATCH  8
#define SEQ    512
#define DMODEL 512
#define NHEAD  8
#define HEADD  64
#define FFDIM  2048
#define NLAYER 6
#define VOCAB  50257
#define VPAD   50304
#define BS     (BATCH*SEQ)
#define QKVS   1536
static const long long NLOG = (long long)BS * VOCAB;

// converted-weight layout (bf16), per layer:
// [q_hi k_hi v_hi o_hi][q_lo k_lo v_lo o_lo][w1_hi w1_lo][w2_hi w2_lo]
#define DDSZ   (DMODEL*DMODEL)
#define DFSZ   (DMODEL*FFDIM)
#define QKVO_TOT (8*DDSZ)
#define WL_STRIDE (QKVO_TOT + 2*DFSZ + 2*DFSZ)

// ---------------- device scratch ----------------
__device__ float g_h[BS * DMODEL];
__device__ float g_rowloss[BS];
__device__ float g_bqkv[NLAYER * QKVS];
__device__ float g_logits_scratch[(size_t)BS * VOCAB];
__device__ __nv_bfloat16 g_xnh[BS * DMODEL];
__device__ __nv_bfloat16 g_xnl[BS * DMODEL];
__device__ __nv_bfloat16 g_qkvh[BS * QKVS];
__device__ __nv_bfloat16 g_qkvl[BS * QKVS];
__device__ __nv_bfloat16 g_ctxh[BS * DMODEL];
__device__ __nv_bfloat16 g_ctxl[BS * DMODEL];
__device__ __nv_bfloat16 g_ffh[BS * FFDIM];
__device__ __nv_bfloat16 g_ffl[BS * FFDIM];
__device__ __nv_bfloat16 g_wbuf[(size_t)WL_STRIDE * NLAYER];
__device__ __nv_bfloat16 g_emb[2 * (size_t)VPAD * DMODEL];

// ================= PTX helpers =================
__device__ __forceinline__ uint32_t smem_to_u32(const void* smem_ptr) {
    uint32_t addr;
    asm("{ .reg .u64 tmp; cvta.to.shared.u64 tmp, %1; cvt.u32.u64 %0, tmp; }"
        : "=r"(addr) : "l"(smem_ptr));
    return addr;
}
__device__ __forceinline__ void cp16(uint32_t d, const void* s, int sz) {
    asm volatile("cp.async.cg.shared.global [%0], [%1], 16, %2;\n"
                 :: "r"(d), "l"(s), "r"(sz) : "memory");
}
__device__ __forceinline__ void cp_commit() {
    asm volatile("cp.async.commit_group;\n" ::: "memory");
}
__device__ __forceinline__ void cp_wait0() {
    asm volatile("cp.async.wait_group 0;\n" ::: "memory");
}
__device__ __forceinline__ void cp_wait1() {
    asm volatile("cp.async.wait_group 1;\n" ::: "memory");
}
#define LDSM4(r, addr) \
    asm volatile("ldmatrix.sync.aligned.m8n8.x4.shared.b16 {%0,%1,%2,%3}, [%4];" \
        : "=r"((r)[0]), "=r"((r)[1]), "=r"((r)[2]), "=r"((r)[3]) : "r"(addr))
#define MMA16816(c, a, b0, b1) \
    asm volatile("mma.sync.aligned.m16n8k16.row.col.f32.bf16.bf16.f32 " \
        "{%0,%1,%2,%3}, {%4,%5,%6,%7}, {%8,%9}, {%0,%1,%2,%3};" \
        : "+f"((c)[0]), "+f"((c)[1]), "+f"((c)[2]), "+f"((c)[3]) \
        : "r"((a)[0]), "r"((a)[1]), "r"((a)[2]), "r"((a)[3]), "r"(b0), "r"(b1))

__device__ __forceinline__ void split4(float4 v, uint2& hi, uint2& lo) {
    __nv_bfloat162 h01 = __floats2bfloat162_rn(v.x, v.y);
    __nv_bfloat162 h23 = __floats2bfloat162_rn(v.z, v.w);
    float2 b01 = __bfloat1622float2(h01);
    float2 b23 = __bfloat1622float2(h23);
    __nv_bfloat162 l01 = __floats2bfloat162_rn(v.x - b01.x, v.y - b01.y);
    __nv_bfloat162 l23 = __floats2bfloat162_rn(v.z - b23.x, v.w - b23.y);
    hi.x = *reinterpret_cast<uint32_t*>(&h01);
    hi.y = *reinterpret_cast<uint32_t*>(&h23);
    lo.x = *reinterpret_cast<uint32_t*>(&l01);
    lo.y = *reinterpret_cast<uint32_t*>(&l23);
}

// ---------------- GEMM smem layout ----------------
#define TB 16384
#define STAGE_BYTES (4*TB)
#define SMEM_OFF 1024
#define GEMM_SMEM (SMEM_OFF + 2*STAGE_BYTES)

__device__ __forceinline__ void copy_stage(uint32_t st,
        const __nv_bfloat16* __restrict__ Ahi, const __nv_bfloat16* __restrict__ Alo,
        const __nv_bfloat16* __restrict__ Bhi, const __nv_bfloat16* __restrict__ Blo,
        int bm, int bn, int k0, int K, int N, int tid) {
    #pragma unroll
    for (int it = 0; it < 4; it++) {
        int idx = tid + it * 256;
        int row = idx >> 3, c = idx & 7;
        uint32_t d = st + row * 128 + ((c ^ (row & 7)) << 4);
        size_t so = (size_t)(bm + row) * K + k0 + c * 8;
        cp16(d, Ahi + so, 16);
        cp16(d + TB, Alo + so, 16);
    }
    #pragma unroll
    for (int it = 0; it < 4; it++) {
        int idx = tid + it * 256;
        int row = idx >> 3, c = idx & 7;
        int n = bn + row;
        int sz = (n < N) ? 16 : 0;
        uint32_t d = st + 2 * TB + row * 128 + ((c ^ (row & 7)) << 4);
        size_t so = (size_t)n * K + k0 + c * 8;
        cp16(d, Bhi + so, sz);
        cp16(d + TB, Blo + so, sz);
    }
}

// epilogue: 0=bias->f32, 1=bias+res->f32, 2=bias+gelu->bf16 split, 3=plain f32, 4=bias->bf16 split
template <int EPI>
__device__ __forceinline__ void emit_one(float x, size_t off, int col,
        const float* __restrict__ bias, const float* __restrict__ res,
        float* __restrict__ C, __nv_bfloat16* __restrict__ Chi, __nv_bfloat16* __restrict__ Clo) {
    if (EPI == 0 || EPI == 1 || EPI == 2 || EPI == 4) x += __ldg(bias + col);
    if (EPI == 2) x = 0.5f * x * (1.0f + erff(x * 0.70710678118654752440f));
    if (EPI == 1) x += res[off];
    if (EPI == 2 || EPI == 4) {
        __nv_bfloat16 h = __float2bfloat16(x);
        Chi[off] = h;
        Clo[off] = __float2bfloat16(x - __bfloat162float(h));
    } else {
        C[off] = x;
    }
}

// ---------------- GEMM: C[M,N] = (Ahi+Alo)(Bhi+Blo)^T split-compensated ----------------
template <int EPI>
__global__ void __launch_bounds__(256, 1)
gemm_bf(const __nv_bfloat16* __restrict__ Ahi, const __nv_bfloat16* __restrict__ Alo,
        const __nv_bfloat16* __restrict__ Bhi, const __nv_bfloat16* __restrict__ Blo,
        const float* __restrict__ bias, const float* __restrict__ res,
        float* __restrict__ C, __nv_bfloat16* __restrict__ Chi, __nv_bfloat16* __restrict__ Clo,
        int M, int N, int K) {
    extern __shared__ char smem[];
    const int tid = threadIdx.x;
    const int bm = blockIdx.x * 128;
    const int bn = blockIdx.y * 128;
    const int nc = K >> 6;

    const uint32_t tiles = smem_to_u32(smem) + SMEM_OFF;
    const int lane = tid & 31;
    const int wid = tid >> 5;
    const int wm = (wid & 3) << 5;
    const int wn = (wid >> 2) << 6;
    const int mi = lane >> 3;
    const int lrow = lane & 7;

    float acc[2][8][4];
    #pragma unroll
    for (int i = 0; i < 2; i++)
        #pragma unroll
        for (int j = 0; j < 8; j++)
            #pragma unroll
            for (int t = 0; t < 4; t++) acc[i][j][t] = 0.0f;

    copy_stage(tiles, Ahi, Alo, Bhi, Blo, bm, bn, 0, K, N, tid);
    cp_commit();

    uint32_t st;
    uint32_t fah[2][2][4], fal[2][2][4], fbh[2][4][4], fbl[2][4][4];
#define GLOAD(s_, d_) do { \
        const int cb_ = ((s_) << 5) + ((mi >> 1) << 4); \
        _Pragma("unroll") \
        for (int i_ = 0; i_ < 2; i_++) { \
            int r_ = wm + (i_ << 4) + ((mi & 1) << 3) + lrow; \
            uint32_t a_ = st + r_ * 128 + (cb_ ^ ((r_ & 7) << 4)); \
            LDSM4(fah[d_][i_], a_); \
            LDSM4(fal[d_][i_], a_ + TB); \
        } \
        _Pragma("unroll") \
        for (int j_ = 0; j_ < 4; j_++) { \
            int r_ = wn + (j_ << 4) + ((mi & 1) << 3) + lrow; \
            uint32_t a_ = st + 2 * TB + r_ * 128 + (cb_ ^ ((r_ & 7) << 4)); \
            LDSM4(fbh[d_][j_], a_); \
            LDSM4(fbl[d_][j_], a_ + TB); \
        } \
    } while (0)

    for (int c = 0; c < nc; c++) {
        if (c + 1 < nc) {
            copy_stage(tiles + ((c + 1) & 1) * STAGE_BYTES, Ahi, Alo, Bhi, Blo,
                       bm, bn, (c + 1) << 6, K, N, tid);
            cp_commit();
            cp_wait1();
        } else {
            cp_wait0();
        }
        __syncthreads();

        st = tiles + (c & 1) * STAGE_BYTES;
        GLOAD(0, 0);
        #pragma unroll
        for (int s = 0; s < 4; s++) {
            const int cur = s & 1, nxt = cur ^ 1;
            if (s < 3) GLOAD(s + 1, nxt);
            #pragma unroll
            for (int i = 0; i < 2; i++)
                #pragma unroll
                for (int j2 = 0; j2 < 4; j2++) {
                    MMA16816(acc[i][2 * j2],     fah[cur][i], fbh[cur][j2][0], fbh[cur][j2][2]);
                    MMA16816(acc[i][2 * j2 + 1], fah[cur][i], fbh[cur][j2][1], fbh[cur][j2][3]);
                }
            #pragma unroll
            for (int i = 0; i < 2; i++)
                #pragma unroll
                for (int j2 = 0; j2 < 4; j2++) {
                    MMA16816(acc[i][2 * j2],     fal[cur][i], fbh[cur][j2][0], fbh[cur][j2][2]);
                    MMA16816(acc[i][2 * j2 + 1], fal[cur][i], fbh[cur][j2][1], fbh[cur][j2][3]);
                }
            #pragma unroll
            for (int i = 0; i < 2; i++)
                #pragma unroll
                for (int j2 = 0; j2 < 4; j2++) {
                    MMA16816(acc[i][2 * j2],     fah[cur][i], fbl[cur][j2][0], fbl[cur][j2][2]);
                    MMA16816(acc[i][2 * j2 + 1], fah[cur][i], fbl[cur][j2][1], fbl[cur][j2][3]);
                }
        }
        __syncthreads();
    }
#undef GLOAD

    #pragma unroll
    for (int i = 0; i < 2; i++) {
        int row = bm + wm + (i << 4) + (lane >> 2);
        size_t base = (size_t)row * N;
        size_t base8 = base + (size_t)8 * N;
        #pragma unroll
        for (int j = 0; j < 8; j++) {
            int col = bn + wn + (j << 3) + ((lane & 3) << 1);
            if (col < N)     emit_one<EPI>(acc[i][j][0], base + col, col, bias, res, C, Chi, Clo);
            if (col + 1 < N) emit_one<EPI>(acc[i][j][1], base + col + 1, col + 1, bias, res, C, Chi, Clo);
            if (col < N)     emit_one<EPI>(acc[i][j][2], base8 + col, col, bias, res, C, Chi, Clo);
            if (col + 1 < N) emit_one<EPI>(acc[i][j][3], base8 + col + 1, col + 1, bias, res, C, Chi, Clo);
        }
    }
}

// ---------------- flash attention (mma.sync, split-compensated) ----------------
#define ATT_SMEM (6*16384)
__global__ void __launch_bounds__(256, 1)
fattn_k(const __nv_bfloat16* __restrict__ qkvh, const __nv_bfloat16* __restrict__ qkvl,
        __nv_bfloat16* __restrict__ ch, __nv_bfloat16* __restrict__ cl) {
    extern __shared__ char smx[];
    const uint32_t sQ = smem_to_u32(smx);
    const uint32_t sK = sQ + 2 * 16384;
    const uint32_t sV = sQ + 4 * 16384;
    const int tid = threadIdx.x;
    const int lane = tid & 31, wid = tid >> 5;
    const int qt = blockIdx.x;
    const int bh = blockIdx.y;
    const int b = bh >> 3, h = bh & 7;
    const int tokQ = b * SEQ + qt * 128;
    const int ho = h * HEADD;
    const int mi = lane >> 3, lrow = lane & 7;
    const int wm = wid * 16;
    const int rB = ((mi & 1) << 3) + lrow;

    // ---- load Q tile (hi/lo)
    #pragma unroll
    for (int it = 0; it < 4; it++) {
        int idx = tid + it * 256;
        int r = idx >> 3, c = idx & 7;
        uint32_t d = sQ + r * 128 + ((c ^ (r & 7)) << 4);
        size_t so = (size_t)(tokQ + r) * QKVS + ho + c * 8;
        cp16(d, qkvh + so, 16);
        cp16(d + 16384, qkvl + so, 16);
    }
    cp_commit();
    cp_wait0();
    __syncthreads();

    uint32_t aq[4][4], aql[4][4];
    {
        int r = wm + rB;
        #pragma unroll
        for (int s = 0; s < 4; s++) {
            uint32_t addr = sQ + r * 128 + ((((s << 5) + ((mi >> 1) << 4))) ^ ((r & 7) << 4));
            LDSM4(aq[s], addr);
            LDSM4(aql[s], addr + 16384);
        }
    }

    float oacc[8][4];
    #pragma unroll
    for (int f = 0; f < 8; f++)
        #pragma unroll
        for (int t = 0; t < 4; t++) oacc[f][t] = 0.0f;
    float mr0 = -1e30f, mr1 = -1e30f, lr0 = 0.0f, lr1 = 0.0f;
    const int myr0 = wm + (lane >> 2);
    const int myr1 = myr0 + 8;

    for (int jt = 0; jt <= qt; jt++) {
        __syncthreads();
        const int tokJ = b * SEQ + jt * 128;
        #pragma unroll
        for (int it = 0; it < 4; it++) {
            int idx = tid + it * 256;
            int r = idx >> 3, c = idx & 7;
            uint32_t d = sK + r * 128 + ((c ^ (r & 7)) << 4);
            size_t so = (size_t)(tokJ + r) * QKVS + 512 + ho + c * 8;
            cp16(d, qkvh + so, 16);
            cp16(d + 16384, qkvl + so, 16);
        }
        #pragma unroll
        for (int it = 0; it < 4; it++) {
            int task = tid + it * 256;
            int j = task >> 3, c = task & 7;
            size_t so = (size_t)(tokJ + j) * QKVS + 1024 + ho + c * 8;
            uint4 v4h = *reinterpret_cast<const uint4*>(qkvh + so);
            uint4 v4l = *reinterpret_cast<const uint4*>(qkvl + so);
            const uint32_t* wh = &v4h.x;
            const uint32_t* wl = &v4l.x;
            #pragma unroll
            for (int i = 0; i < 8; i++) {
                int dd = c * 8 + i;
                uint32_t off = dd * 256 + ((((uint32_t)(j >> 3) ^ (uint32_t)(dd & 7)) << 4)) + (j & 7) * 2;
                uint16_t hv = (uint16_t)(wh[i >> 1] >> ((i & 1) * 16));
                uint16_t lv = (uint16_t)(wl[i >> 1] >> ((i & 1) * 16));
                asm volatile("st.shared.u16 [%0], %1;" :: "r"(sV + off), "h"(hv));
                asm volatile("st.shared.u16 [%0], %1;" :: "r"(sV + 16384 + off), "h"(lv));
            }
        }
        cp_commit();
        cp_wait0();
        __syncthreads();

        // ---- S = Q K^T (3-pass split), frag-prefetched
        float facc[16][4];
        #pragma unroll
        for (int f = 0; f < 16; f++)
            #pragma unroll
            for (int t = 0; t < 4; t++) facc[f][t] = 0.0f;
        {
            uint32_t kb[2][4], kbl[2][4];
            {
                int r = rB;
                uint32_t addr = sK + r * 128 + ((((mi >> 1) << 4)) ^ ((r & 7) << 4));
                LDSM4(kb[0], addr);
                LDSM4(kbl[0], addr + 16384);
            }
            #pragma unroll
            for (int gs = 0; gs < 32; gs++) {
                const int g = gs >> 2, s = gs & 3;
                const int cur = gs & 1, nxt = cur ^ 1;
                if (gs < 31) {
                    int g2 = (gs + 1) >> 2, s2 = (gs + 1) & 3;
                    int r = g2 * 16 + rB;
                    uint32_t addr = sK + r * 128 + ((((s2 << 5) + ((mi >> 1) << 4))) ^ ((r & 7) << 4));
                    LDSM4(kb[nxt], addr);
                    LDSM4(kbl[nxt], addr + 16384);
                }
                MMA16816(facc[2 * g],     aq[s],  kb[cur][0],  kb[cur][2]);
                MMA16816(facc[2 * g + 1], aq[s],  kb[cur][1],  kb[cur][3]);
                MMA16816(facc[2 * g],     aql[s], kb[cur][0],  kb[cur][2]);
                MMA16816(facc[2 * g + 1], aql[s], kb[cur][1],  kb[cur][3]);
                MMA16816(facc[2 * g],     aq[s],  kbl[cur][0], kbl[cur][2]);
                MMA16816(facc[2 * g + 1], aq[s],  kbl[cur][1], kbl[cur][3]);
            }
        }
        const float scl = 0.125f;
        #pragma unroll
        for (int f = 0; f < 16; f++) {
            int c0 = f * 8 + 2 * (lane & 3);
            facc[f][0] *= scl; facc[f][1] *= scl;
            facc[f][2] *= scl; facc[f][3] *= scl;
            if (jt == qt) {
                if (c0     > myr0) facc[f][0] = -1e30f;
                if (c0 + 1 > myr0) facc[f][1] = -1e30f;
                if (c0     > myr1) facc[f][2] = -1e30f;
                if (c0 + 1 > myr1) facc[f][3] = -1e30f;
            }
        }
        float m0 = -1e30f, m1 = -1e30f;
        #pragma unroll
        for (int f = 0; f < 16; f++) {
            m0 = fmaxf(m0, fmaxf(facc[f][0], facc[f][1]));
            m1 = fmaxf(m1, fmaxf(facc[f][2], facc[f][3]));
        }
        m0 = fmaxf(m0, __shfl_xor_sync(0xffffffffu, m0, 1));
        m0 = fmaxf(m0, __shfl_xor_sync(0xffffffffu, m0, 2));
        m1 = fmaxf(m1, __shfl_xor_sync(0xffffffffu, m1, 1));
        m1 = fmaxf(m1, __shfl_xor_sync(0xffffffffu, m1, 2));
        float nm0 = fmaxf(mr0, m0), nm1 = fmaxf(mr1, m1);
        float al0 = __expf(mr0 - nm0), al1 = __expf(mr1 - nm1);
        mr0 = nm0; mr1 = nm1;
        #pragma unroll
        for (int f = 0; f < 8; f++) {
            oacc[f][0] *= al0; oacc[f][1] *= al0;
            oacc[f][2] *= al1; oacc[f][3] *= al1;
        }
        float s0 = 0.0f, s1 = 0.0f;
        uint32_t pah[8][4], pal[8][4];
        #pragma unroll
        for (int f = 0; f < 16; f++) {
            float p0 = __expf(facc[f][0] - nm0);
            float p1 = __expf(facc[f][1] - nm0);
            float p2 = __expf(facc[f][2] - nm1);
            float p3 = __expf(facc[f][3] - nm1);
            s0 += p0 + p1;
            s1 += p2 + p3;
            __nv_bfloat162 hp = __floats2bfloat162_rn(p0, p1);
            float2 hf = __bfloat1622float2(hp);
            __nv_bfloat162 lp = __floats2bfloat162_rn(p0 - hf.x, p1 - hf.y);
            __nv_bfloat162 hq = __floats2bfloat162_rn(p2, p3);
            float2 hg = __bfloat1622float2(hq);
            __nv_bfloat162 lq = __floats2bfloat162_rn(p2 - hg.x, p3 - hg.y);
            int ks = f >> 1, half = f & 1;
            pah[ks][2 * half]     = *reinterpret_cast<uint32_t*>(&hp);
            pah[ks][2 * half + 1] = *reinterpret_cast<uint32_t*>(&hq);
            pal[ks][2 * half]     = *reinterpret_cast<uint32_t*>(&lp);
            pal[ks][2 * half + 1] = *reinterpret_cast<uint32_t*>(&lq);
        }
        s0 += __shfl_xor_sync(0xffffffffu, s0, 1);
        s0 += __shfl_xor_sync(0xffffffffu, s0, 2);
        s1 += __shfl_xor_sync(0xffffffffu, s1, 1);
        s1 += __shfl_xor_sync(0xffffffffu, s1, 2);
        lr0 = lr0 * al0 + s0;
        lr1 = lr1 * al1 + s1;
        // ---- O += P V (3-pass split), frag-prefetched
        {
            uint32_t vb[2][4], vbl[2][4];
            {
                int r = rB;
                uint32_t addr = sV + r * 256 + ((((mi >> 1) << 4)) ^ ((r & 7) << 4));
                LDSM4(vb[0], addr);
                LDSM4(vbl[0], addr + 16384);
            }
            #pragma unroll
            for (int t = 0; t < 32; t++) {
                const int ks = t >> 2, g2 = t & 3;
                const int cur = t & 1, nxt = cur ^ 1;
                if (t < 31) {
                    int ks2 = (t + 1) >> 2, g22 = (t + 1) & 3;
                    int r = g22 * 16 + rB;
                    uint32_t addr = sV + r * 256 + ((((ks2 << 5) + ((mi >> 1) << 4))) ^ ((r & 7) << 4));
                    LDSM4(vb[nxt], addr);
                    LDSM4(vbl[nxt], addr + 16384);
                }
                MMA16816(oacc[2 * g2],     pah[ks], vb[cur][0],  vb[cur][2]);
                MMA16816(oacc[2 * g2 + 1], pah[ks], vb[cur][1],  vb[cur][3]);
                MMA16816(oacc[2 * g2],     pal[ks], vb[cur][0],  vb[cur][2]);
                MMA16816(oacc[2 * g2 + 1], pal[ks], vb[cur][1],  vb[cur][3]);
                MMA16816(oacc[2 * g2],     pah[ks], vbl[cur][0], vbl[cur][2]);
                MMA16816(oacc[2 * g2 + 1], pah[ks], vbl[cur][1], vbl[cur][3]);
            }
        }
    }

    float inv0 = 1.0f / lr0, inv1 = 1.0f / lr1;
    size_t t0 = (size_t)(tokQ + myr0) * DMODEL + ho;
    size_t t1 = t0 + (size_t)8 * DMODEL;
    #pragma unroll
    for (int f = 0; f < 8; f++) {
        int dc = f * 8 + 2 * (lane & 3);
        float x0 = oacc[f][0] * inv0, x1 = oacc[f][1] * inv0;
        float x2 = oacc[f][2] * inv1, x3 = oacc[f][3] * inv1;
        __nv_bfloat162 h01 = __floats2bfloat162_rn(x0, x1);
        float2 hf = __bfloat1622float2(h01);
        __nv_bfloat162 l01 = __floats2bfloat162_rn(x0 - hf.x, x1 - hf.y);
        __nv_bfloat162 h23 = __floats2bfloat162_rn(x2, x3);
        float2 hg = __bfloat1622float2(h23);
        __nv_bfloat162 l23 = __floats2bfloat162_rn(x2 - hg.x, x3 - hg.y);
        *reinterpret_cast<uint32_t*>(ch + t0 + dc) = *reinterpret_cast<uint32_t*>(&h01);
        *reinterpret_cast<uint32_t*>(cl + t0 + dc) = *reinterpret_cast<uint32_t*>(&l01);
        *reinterpret_cast<uint32_t*>(ch + t1 + dc) = *reinterpret_cast<uint32_t*>(&h23);
        *reinterpret_cast<uint32_t*>(cl + t1 + dc) = *reinterpret_cast<uint32_t*>(&l23);
    }
}

// ---------------- weight transpose + split ----------------
__device__ __forceinline__ void transpose_split(const float* __restrict__ in,
        __nv_bfloat16* __restrict__ hi, __nv_bfloat16* __restrict__ lo, int K, int N) {
    __shared__ float t[32][33];
    int n0 = blockIdx.x << 5, k0 = blockIdx.y << 5;
    int tx = threadIdx.x, ty = threadIdx.y;
    #pragma unroll
    for (int r = 0; r < 4; r++)
        t[ty + 8 * r][tx] = in[(size_t)(k0 + ty + 8 * r) * N + n0 + tx];
    __syncthreads();
    #pragma unroll
    for (int r = 0; r < 4; r++) {
        float v = t[tx][ty + 8 * r];
        size_t o = (size_t)(n0 + ty + 8 * r) * K + k0 + tx;
        __nv_bfloat16 h = __float2bfloat16(v);
        hi[o] = h;
        lo[o] = __float2bfloat16(v - __bfloat162float(h));
    }
}
__global__ void wsplit_qkvo_k(const float* __restrict__ Wq, const float* __restrict__ Wk,
                              const float* __restrict__ Wv, const float* __restrict__ Wo,
                              __nv_bfloat16* __restrict__ wbuf) {
    int z = blockIdx.z, l = z >> 2, m = z & 3;
    const float* W = (m == 0 ? Wq : m == 1 ? Wk : m == 2 ? Wv : Wo) + (size_t)l * DDSZ;
    __nv_bfloat16* base = wbuf + (size_t)l * WL_STRIDE;
    transpose_split(W, base + (size_t)m * DDSZ, base + (size_t)(4 + m) * DDSZ, DMODEL, DMODEL);
}
__global__ void wsplit_w1_k(const float* __restrict__ W1, __nv_bfloat16* __restrict__ wbuf) {
    int l = blockIdx.z;
    __nv_bfloat16* hi = wbuf + (size_t)l * WL_STRIDE + QKVO_TOT;
    transpose_split(W1 + (size_t)l * DFSZ, hi, hi + DFSZ, DMODEL, FFDIM);
}
__global__ void wsplit_w2_k(const float* __restrict__ W2, __nv_bfloat16* __restrict__ wbuf) {
    int l = blockIdx.z;
    __nv_bfloat16* hi = wbuf + (size_t)l * WL_STRIDE + QKVO_TOT + 2 * (size_t)DFSZ;
    transpose_split(W2 + (size_t)l * DFSZ, hi, hi + DFSZ, FFDIM, DMODEL);
}
__global__ __launch_bounds__(256) void embsplit_k(const float* __restrict__ te,
        __nv_bfloat16* __restrict__ hi, __nv_bfloat16* __restrict__ lo) {
    size_t n4 = (size_t)VOCAB * DMODEL / 4;
    for (size_t i = (size_t)blockIdx.x * blockDim.x + threadIdx.x; i < n4;
         i += (size_t)gridDim.x * blockDim.x) {
        float4 v = reinterpret_cast<const float4*>(te)[i];
        uint2 h, l;
        split4(v, h, l);
        reinterpret_cast<uint2*>(hi)[i] = h;
        reinterpret_cast<uint2*>(lo)[i] = l;
    }
}
__global__ void biascat_k(const float* __restrict__ bq, const float* __restrict__ bk,
                          const float* __restrict__ bv, float* __restrict__ o) {
    int l = blockIdx.x, t = threadIdx.x;
    o[l * QKVS + t]        = bq[l * DMODEL + t];
    o[l * QKVS + 512 + t]  = bk[l * DMODEL + t];
    o[l * QKVS + 1024 + t] = bv[l * DMODEL + t];
}

// ---------------- helpers ----------------
__device__ __forceinline__ int detect_i64(const void* p, int n) {
    const long long* x = (const long long*)p;
    int c = n < 32 ? n : 32;
    for (int i = 0; i < c; i++) {
        long long v = x[i];
        if (v < 0 || v >= VOCAB) return 0;
    }
    return 1;
}
__device__ __forceinline__ long long load_index(const void* p, int i, int is64) {
    return is64 ? ((const long long*)p)[i] : (long long)((const int*)p)[i];
}

// ---------------- embedding ----------------
__global__ __launch_bounds__(256) void embed_k(const void* __restrict__ xr,
                                               const float* __restrict__ te,
                                               const float* __restrict__ pe,
                                               float* __restrict__ h) {
    __shared__ int mode;
    if (threadIdx.x == 0) mode = detect_i64(xr, BS);
    __syncthreads();
    int pos = blockIdx.x;
    int tid = threadIdx.x;
    long long idx = load_index(xr, pos, mode);
    int s = pos & (SEQ - 1);
    const float* t = te + idx * DMODEL;
    const float* p = pe + (long long)s * DMODEL;
    float* o = h + (long long)pos * DMODEL;
    o[tid]       = t[tid]       + p[tid];
    o[tid + 256] = t[tid + 256] + p[tid + 256];
}

// ---------------- layernorm -> bf16 split (warp-shuffle reductions) ----------------
__global__ __launch_bounds__(256) void ln_k(const float* __restrict__ in,
                                            const float* __restrict__ g,
                                            const float* __restrict__ b,
                                            __nv_bfloat16* __restrict__ oh,
                                            __nv_bfloat16* __restrict__ ol) {
    int row = blockIdx.x;
    int tid = threadIdx.x;
    int lane = tid & 31, wid = tid >> 5;
    const float* x = in + (long long)row * DMODEL;
    float v0 = x[tid], v1 = x[tid + 256];
    __shared__ float wr[16];
    float s = v0 + v1;
    #pragma unroll
    for (int o = 16; o; o >>= 1) s += __shfl_xor_sync(0xffffffffu, s, o);
    if (lane == 0) wr[wid] = s;
    __syncthreads();
    float mu = (wr[0] + wr[1] + wr[2] + wr[3] + wr[4] + wr[5] + wr[6] + wr[7]) * (1.0f / DMODEL);
    float d0 = v0 - mu, d1 = v1 - mu;
    float q = d0 * d0 + d1 * d1;
    #pragma unroll
    for (int o = 16; o; o >>= 1) q += __shfl_xor_sync(0xffffffffu, q, o);
    if (lane == 0) wr[8 + wid] = q;
    __syncthreads();
    float var = (wr[8] + wr[9] + wr[10] + wr[11] + wr[12] + wr[13] + wr[14] + wr[15]) * (1.0f / DMODEL);
    float rstd = rsqrtf(var + 1e-5f);
    long long base = (long long)row * DMODEL;
    float y0 = d0 * rstd * g[tid] + b[tid];
    float y1 = d1 * rstd * g[tid + 256] + b[tid + 256];
    __nv_bfloat16 h0 = __float2bfloat16(y0);
    __nv_bfloat16 h1 = __float2bfloat16(y1);
    oh[base + tid] = h0;
    ol[base + tid] = __float2bfloat16(y0 - __bfloat162float(h0));
    oh[base + tid + 256] = h1;
    ol[base + tid + 256] = __float2bfloat16(y1 - __bfloat162float(h1));
}

// ---------------- single-pass cross-entropy ----------------
__global__ __launch_bounds__(256) void loss_row_k(const float* __restrict__ logits,
                                                  const void* __restrict__ tr,
                                                  float* __restrict__ rowloss) {
    __shared__ int mode;
    __shared__ float rm[256], rs[256];
    int row = blockIdx.x, tid = threadIdx.x;
    if (tid == 0) mode = detect_i64(tr, BS);
    __syncthreads();
    const float* lr = logits + (long long)row * VOCAB;
    float m = -1e30f, s = 0.0f;
    for (int j = tid; j < VOCAB; j += 256) {
        float v = lr[j];
        float nm = fmaxf(m, v);
        s = s * __expf(m - nm) + __expf(v - nm);
        m = nm;
    }
    rm[tid] = m;
    rs[tid] = s;
    __syncthreads();
    #pragma unroll
    for (int st = 128; st > 0; st >>= 1) {
        if (tid < st) {
            float ma = rm[tid], mb = rm[tid + st];
            float nm = fmaxf(ma, mb);
            rs[tid] = rs[tid] * __expf(ma - nm) + rs[tid + st] * __expf(mb - nm);
            rm[tid] = nm;
        }
        __syncthreads();
    }
    if (tid == 0) {
        long long t = load_index(tr, row, mode);
        rowloss[row] = -(lr[t] - rm[0] - logf(rs[0]));
    }
}

__global__ __launch_bounds__(1024) void loss_reduce_k(const float* __restrict__ rowloss,
                                                      float* __restrict__ out) {
    __shared__ float red[1024];
    int tid = threadIdx.x;
    red[tid] = rowloss[tid] + rowloss[tid + 1024] + rowloss[tid + 2048] + rowloss[tid + 3072];
    __syncthreads();
    #pragma unroll
    for (int s = 512; s > 0; s >>= 1) {
        if (tid < s) red[tid] += red[tid + s];
        __syncthreads();
    }
    if (tid == 0) out[0] = red[0] * (1.0f / BS);
}

// ---------------- host launcher ----------------
extern "C" void kernel_launch(void* const* d_in, const int* in_sizes, int n_in,
                              void* d_out, int out_size) {
    (void)in_sizes; (void)n_in;
    const void*  x       = d_in[0];
    const void*  targets = d_in[1];
    const float* te   = (const float*)d_in[2];
    const float* pe   = (const float*)d_in[3];
    const float* ln1g = (const float*)d_in[4];
    const float* ln1b = (const float*)d_in[5];
    const float* Wq   = (const float*)d_in[6];
    const float* bq   = (const float*)d_in[7];
    const float* Wk   = (const float*)d_in[8];
    const float* bk   = (const float*)d_in[9];
    const float* Wv   = (const float*)d_in[10];
    const float* bv   = (const float*)d_in[11];
    const float* Wo   = (const float*)d_in[12];
    const float* bo   = (const float*)d_in[13];
    const float* ln2g = (const float*)d_in[14];
    const float* ln2b = (const float*)d_in[15];
    const float* W1   = (const float*)d_in[16];
    const float* b1   = (const float*)d_in[17];
    const float* W2   = (const float*)d_in[18];
    const float* b2   = (const float*)d_in[19];
    const float* lnfg = (const float*)d_in[20];
    const float* lnfb = (const float*)d_in[21];
    float* out = (float*)d_out;

    float *p_h, *p_rowloss, *p_logits, *p_bqkv;
    __nv_bfloat16 *p_xnh, *p_xnl, *p_qkvh, *p_qkvl;
    __nv_bfloat16 *p_ctxh, *p_ctxl, *p_ffh, *p_ffl, *p_wbuf, *p_emb;
    cudaGetSymbolAddress((void**)&p_h, g_h);
    cudaGetSymbolAddress((void**)&p_rowloss, g_rowloss);
    cudaGetSymbolAddress((void**)&p_logits, g_logits_scratch);
    cudaGetSymbolAddress((void**)&p_bqkv, g_bqkv);
    cudaGetSymbolAddress((void**)&p_xnh, g_xnh);
    cudaGetSymbolAddress((void**)&p_xnl, g_xnl);
    cudaGetSymbolAddress((void**)&p_qkvh, g_qkvh);
    cudaGetSymbolAddress((void**)&p_qkvl, g_qkvl);
    cudaGetSymbolAddress((void**)&p_ctxh, g_ctxh);
    cudaGetSymbolAddress((void**)&p_ctxl, g_ctxl);
    cudaGetSymbolAddress((void**)&p_ffh, g_ffh);
    cudaGetSymbolAddress((void**)&p_ffl, g_ffl);
    cudaGetSymbolAddress((void**)&p_wbuf, g_wbuf);
    cudaGetSymbolAddress((void**)&p_emb, g_emb);
    __nv_bfloat16* p_embh = p_emb;
    __nv_bfloat16* p_embl = p_emb + (size_t)VPAD * DMODEL;

    cudaFuncSetAttribute(gemm_bf<0>, cudaFuncAttributeMaxDynamicSharedMemorySize, GEMM_SMEM);
    cudaFuncSetAttribute(gemm_bf<1>, cudaFuncAttributeMaxDynamicSharedMemorySize, GEMM_SMEM);
    cudaFuncSetAttribute(gemm_bf<2>, cudaFuncAttributeMaxDynamicSharedMemorySize, GEMM_SMEM);
    cudaFuncSetAttribute(gemm_bf<3>, cudaFuncAttributeMaxDynamicSharedMemorySize, GEMM_SMEM);
    cudaFuncSetAttribute(gemm_bf<4>, cudaFuncAttributeMaxDynamicSharedMemorySize, GEMM_SMEM);
    cudaFuncSetAttribute(fattn_k, cudaFuncAttributeMaxDynamicSharedMemorySize, ATT_SMEM);

    wsplit_qkvo_k<<<dim3(16, 16, 24), dim3(32, 8)>>>(Wq, Wk, Wv, Wo, p_wbuf);
    wsplit_w1_k<<<dim3(64, 16, 6), dim3(32, 8)>>>(W1, p_wbuf);
    wsplit_w2_k<<<dim3(16, 64, 6), dim3(32, 8)>>>(W2, p_wbuf);
    embsplit_k<<<2048, 256>>>(te, p_embh, p_embl);
    biascat_k<<<NLAYER, 512>>>(bq, bk, bv, p_bqkv);

    embed_k<<<BS, 256>>>(x, te, pe, p_h);

    dim3 gDD(BS / 128, DMODEL / 128);
    dim3 gQKV(BS / 128, QKVS / 128);
    dim3 gDF(BS / 128, FFDIM / 128);
    dim3 gATT(SEQ / 128, BATCH * NHEAD);

    for (int l = 0; l < NLAYER; l++) {
        __nv_bfloat16* wl = p_wbuf + (size_t)l * WL_STRIDE;
        __nv_bfloat16* w1h = wl + QKVO_TOT;
        __nv_bfloat16* w2h = wl + QKVO_TOT + 2 * (size_t)DFSZ;

        ln_k<<<BS, 256>>>(p_h, ln1g + l * DMODEL, ln1b + l * DMODEL, p_xnh, p_xnl);
        gemm_bf<4><<<gQKV, 256, GEMM_SMEM>>>(p_xnh, p_xnl, wl, wl + 4 * (size_t)DDSZ,
                                             p_bqkv + l * QKVS, nullptr, nullptr,
                                             p_qkvh, p_qkvl, BS, QKVS, DMODEL);
        fattn_k<<<gATT, 256, ATT_SMEM>>>(p_qkvh, p_qkvl, p_ctxh, p_ctxl);
        gemm_bf<1><<<gDD, 256, GEMM_SMEM>>>(p_ctxh, p_ctxl, wl + 3 * (size_t)DDSZ,
                                            wl + 7 * (size_t)DDSZ, bo + l * DMODEL,
                                            p_h, p_h, nullptr, nullptr, BS, DMODEL, DMODEL);
        ln_k<<<BS, 256>>>(p_h, ln2g + l * DMODEL, ln2b + l * DMODEL, p_xnh, p_xnl);
        gemm_bf<2><<<gDF, 256, GEMM_SMEM>>>(p_xnh, p_xnl, w1h, w1h + DFSZ, b1 + l * FFDIM,
                                            nullptr, nullptr, p_ffh, p_ffl, BS, FFDIM, DMODEL);
        gemm_bf<1><<<gDD, 256, GEMM_SMEM>>>(p_ffh, p_ffl, w2h, w2h + DFSZ, b2 + l * DMODEL,
                                            p_h, p_h, nullptr, nullptr, BS, DMODEL, FFDIM);
    }

    ln_k<<<BS, 256>>>(p_h, lnfg, lnfb, p_xnh, p_xnl);

    float* logits = ((long long)out_size >= NLOG) ? out : p_logits;
    dim3 gLOG(BS / 128, VPAD / 128);
    gemm_bf<3><<<gLOG, 256, GEMM_SMEM>>>(p_xnh, p_xnl, p_embh, p_embl, nullptr,
                                         nullptr, logits, nullptr, nullptr, BS, VOCAB, DMODEL);

    loss_row_k<<<BS, 256>>>(logits, targets, p_rowloss);
    if ((long long)out_size > NLOG) {
        loss_reduce_k<<<1, 1024>>>(p_rowloss, out + NLOG);
    } else if ((long long)out_size < NLOG && out_size >= 1) {
        loss_reduce_k<<<1, 1024>>>(p_rowloss, out + (out_size - 1));
    }
}